// round 7
// baseline (speedup 1.0000x reference)
#include <cuda_runtime.h>
#include <cstdint>

#define NB 4
#define LL 4096
#define HH 16
#define DD 64
#define MM 64
#define CC 128
#define GG 32
#define EPS 1e-6f

// smem strides (floats)
#define SA 68    // row-pattern (sq, sk)
#define SB 72    // col-pattern (sv, state)
#define SSW 132  // S tile

// smem layout (floats)
#define OFF_SQ   0
#define OFF_SK   (OFF_SQ + CC*SA)      // 8704
#define OFF_SV   (OFF_SK + CC*SA)      // 17408
#define OFF_SS   (OFF_SV + CC*SB)      // 26624
#define OFF_KVF  (OFF_SS + CC*SSW)     // 43520  state fp32 master [d][m] stride SB
#define OFF_KVT  (OFF_KVF + DD*SB)     // 48128  state tf32 copy
#define OFF_KSUM (OFF_KVT + DD*SB)     // 52736
#define OFF_ZP   (OFF_KSUM + DD)       // 52800  [2][CC]
#define OFF_Z    (OFF_ZP + 2*CC)       // 53056
#define SMF      (OFF_Z + CC)          // 53184
#define SMEMB    (SMF * 4)             // 212736 bytes

__device__ __forceinline__ float phi(float x) { return x > 0.f ? x + 1.f : __expf(x); }
__device__ __forceinline__ float f2tf(float f) {
    uint32_t r; asm("cvt.rna.tf32.f32 %0, %1;" : "=r"(r) : "f"(f)); return __uint_as_float(r);
}
__device__ __forceinline__ void mma8(float c[4], uint32_t a0, uint32_t a1, uint32_t a2, uint32_t a3,
                                     uint32_t b0, uint32_t b1) {
    asm volatile("mma.sync.aligned.m16n8k8.row.col.f32.tf32.tf32.f32 "
                 "{%0,%1,%2,%3},{%4,%5,%6,%7},{%8,%9},{%0,%1,%2,%3};"
                 : "+f"(c[0]), "+f"(c[1]), "+f"(c[2]), "+f"(c[3])
                 : "r"(a0), "r"(a1), "r"(a2), "r"(a3), "r"(b0), "r"(b1));
}

// ---------------------------------------------------------------------------
// Persistent fused kernel: one CTA per (n,h); sequential over 32 chunks.
// ---------------------------------------------------------------------------
__global__ __launch_bounds__(512, 1)
void k_fused(const float* __restrict__ Q, const float* __restrict__ K,
             const float* __restrict__ V, float* __restrict__ O) {
    extern __shared__ float sm[];
    float* sq   = sm + OFF_SQ;
    float* sk   = sm + OFF_SK;
    float* sv   = sm + OFF_SV;
    float* sS   = sm + OFF_SS;
    float* skvf = sm + OFF_KVF;
    float* skvt = sm + OFF_KVT;
    float* sks  = sm + OFF_KSUM;
    float* szp  = sm + OFF_ZP;
    float* sz   = sm + OFF_Z;

    const int tid = threadIdx.x, wid = tid >> 5, lane = tid & 31;
    const int gid = lane >> 2, tg = lane & 3;
    const int nh = blockIdx.x, n = nh >> 4, h = nh & 15;

    // ---- init state ----
    for (int i = tid; i < DD * SB; i += 512) { skvf[i] = 0.f; skvt[i] = 0.f; }
    if (tid < DD) sks[tid] = 0.f;

    // ---- load q,k for chunk 0 ----
    #pragma unroll
    for (int it = 0; it < 4; it++) {
        int idx = tid + it * 512;
        int r = idx >> 4, c0 = (idx & 15) * 4;
        int gb = ((n * LL + r) * HH + h) * DD + c0;
        float4 q4 = *(const float4*)(Q + gb);
        float4 k4 = *(const float4*)(K + gb);
        sq[r * SA + c0 + 0] = f2tf(phi(q4.x));
        sq[r * SA + c0 + 1] = f2tf(phi(q4.y));
        sq[r * SA + c0 + 2] = f2tf(phi(q4.z));
        sq[r * SA + c0 + 3] = f2tf(phi(q4.w));
        sk[r * SA + c0 + 0] = f2tf(phi(k4.x));
        sk[r * SA + c0 + 1] = f2tf(phi(k4.y));
        sk[r * SA + c0 + 2] = f2tf(phi(k4.z));
        sk[r * SA + c0 + 3] = f2tf(phi(k4.w));
    }
    __syncthreads();   // (A) for g=0

    for (int g = 0; g < GG; g++) {
        const int rowbase = n * LL + g * CC;

        // ======== P2: V prefetch + {S | O_inter} ========
        float4 vreg[4];
        #pragma unroll
        for (int it = 0; it < 4; it++) {
            int idx = tid + it * 512;
            int r = idx >> 4, c0 = (idx & 15) * 4;
            vreg[it] = *(const float4*)(V + ((rowbase + r) * HH + h) * DD + c0);
        }

        float cO[2][4][4];   // only warps 8-15 use
        if (wid < 8) {
            // S tile 32 x 64 per warp
            const int r0 = (wid >> 1) * 32, cN0 = (wid & 1) * 64, wn = wid & 1;
            float cS[2][8][4];
            #pragma unroll
            for (int mi = 0; mi < 2; mi++)
                #pragma unroll
                for (int nj = 0; nj < 8; nj++)
                    #pragma unroll
                    for (int q = 0; q < 4; q++) cS[mi][nj][q] = 0.f;

            #pragma unroll
            for (int kk = 0; kk < 8; kk++) {
                int kc = kk * 8 + tg;
                uint32_t a[2][4];
                #pragma unroll
                for (int mi = 0; mi < 2; mi++) {
                    int ar = r0 + mi * 16;
                    a[mi][0] = __float_as_uint(sq[(ar + gid) * SA + kc]);
                    a[mi][1] = __float_as_uint(sq[(ar + 8 + gid) * SA + kc]);
                    a[mi][2] = __float_as_uint(sq[(ar + gid) * SA + kc + 4]);
                    a[mi][3] = __float_as_uint(sq[(ar + 8 + gid) * SA + kc + 4]);
                }
                #pragma unroll
                for (int nj = 0; nj < 8; nj++) {
                    uint32_t b0 = __float_as_uint(sk[(cN0 + nj * 8 + gid) * SA + kc]);
                    uint32_t b1 = __float_as_uint(sk[(cN0 + nj * 8 + gid) * SA + kc + 4]);
                    mma8(cS[0][nj], a[0][0], a[0][1], a[0][2], a[0][3], b0, b1);
                    mma8(cS[1][nj], a[1][0], a[1][1], a[1][2], a[1][3], b0, b1);
                }
            }
            // mask, rowsum partials, store masked S (tf32)
            #pragma unroll
            for (int mi = 0; mi < 2; mi++) {
                int rlo = r0 + mi * 16 + gid, rhi = rlo + 8;
                float zlo = 0.f, zhi = 0.f;
                #pragma unroll
                for (int nj = 0; nj < 8; nj++) {
                    int c0 = cN0 + nj * 8 + 2 * tg, c1 = c0 + 1;
                    float s0 = (c0 <= rlo) ? cS[mi][nj][0] : 0.f;
                    float s1 = (c1 <= rlo) ? cS[mi][nj][1] : 0.f;
                    float s2 = (c0 <= rhi) ? cS[mi][nj][2] : 0.f;
                    float s3 = (c1 <= rhi) ? cS[mi][nj][3] : 0.f;
                    zlo += s0 + s1;
                    zhi += s2 + s3;
                    *(float2*)&sS[rlo * SSW + c0] = make_float2(f2tf(s0), f2tf(s1));
                    *(float2*)&sS[rhi * SSW + c0] = make_float2(f2tf(s2), f2tf(s3));
                }
                zlo += __shfl_xor_sync(0xffffffffu, zlo, 1);
                zlo += __shfl_xor_sync(0xffffffffu, zlo, 2);
                zhi += __shfl_xor_sync(0xffffffffu, zhi, 1);
                zhi += __shfl_xor_sync(0xffffffffu, zhi, 2);
                if (tg == 0) { szp[wn * CC + rlo] = zlo; szp[wn * CC + rhi] = zhi; }
            }
        } else {
            // O_inter = phi(q) @ state : 32 x 32 tile per warp, K=64
            const int widq = wid - 8;
            const int rq0 = (widq >> 1) * 32, ocq = (widq & 1) * 32;
            #pragma unroll
            for (int mi = 0; mi < 2; mi++)
                #pragma unroll
                for (int nj = 0; nj < 4; nj++)
                    #pragma unroll
                    for (int q = 0; q < 4; q++) cO[mi][nj][q] = 0.f;

            #pragma unroll
            for (int kk = 0; kk < 8; kk++) {
                int kc = kk * 8 + tg;
                uint32_t a[2][4];
                #pragma unroll
                for (int mi = 0; mi < 2; mi++) {
                    int ar = rq0 + mi * 16;
                    a[mi][0] = __float_as_uint(sq[(ar + gid) * SA + kc]);
                    a[mi][1] = __float_as_uint(sq[(ar + 8 + gid) * SA + kc]);
                    a[mi][2] = __float_as_uint(sq[(ar + gid) * SA + kc + 4]);
                    a[mi][3] = __float_as_uint(sq[(ar + 8 + gid) * SA + kc + 4]);
                }
                #pragma unroll
                for (int nj = 0; nj < 4; nj++) {
                    uint32_t b0 = __float_as_uint(skvt[kc * SB + ocq + nj * 8 + gid]);
                    uint32_t b1 = __float_as_uint(skvt[(kc + 4) * SB + ocq + nj * 8 + gid]);
                    mma8(cO[0][nj], a[0][0], a[0][1], a[0][2], a[0][3], b0, b1);
                    mma8(cO[1][nj], a[1][0], a[1][1], a[1][2], a[1][3], b0, b1);
                }
            }
        }
        // store v (tf32) to smem
        #pragma unroll
        for (int it = 0; it < 4; it++) {
            int idx = tid + it * 512;
            int r = idx >> 4, c0 = (idx & 15) * 4;
            sv[r * SB + c0 + 0] = f2tf(vreg[it].x);
            sv[r * SB + c0 + 1] = f2tf(vreg[it].y);
            sv[r * SB + c0 + 2] = f2tf(vreg[it].z);
            sv[r * SB + c0 + 3] = f2tf(vreg[it].w);
        }
        __syncthreads();   // (B)

        // ======== P3: q/k prefetch + {O_intra | z+ksum | state update} ========
        float4 qreg[4], kreg[4];
        if (g + 1 < GG) {
            #pragma unroll
            for (int it = 0; it < 4; it++) {
                int idx = tid + it * 512;
                int r = idx >> 4, c0 = (idx & 15) * 4;
                int gb = ((n * LL + (g + 1) * CC + r) * HH + h) * DD + c0;
                qreg[it] = *(const float4*)(Q + gb);
                kreg[it] = *(const float4*)(K + gb);
            }
        }

        if (wid >= 8) {
            // O += S_masked @ V : K=128
            const int widq = wid - 8;
            const int rq0 = (widq >> 1) * 32, ocq = (widq & 1) * 32;
            #pragma unroll
            for (int kk = 0; kk < 16; kk++) {
                int kc = kk * 8 + tg;
                uint32_t a[2][4];
                #pragma unroll
                for (int mi = 0; mi < 2; mi++) {
                    int ar = rq0 + mi * 16;
                    a[mi][0] = __float_as_uint(sS[(ar + gid) * SSW + kc]);
                    a[mi][1] = __float_as_uint(sS[(ar + 8 + gid) * SSW + kc]);
                    a[mi][2] = __float_as_uint(sS[(ar + gid) * SSW + kc + 4]);
                    a[mi][3] = __float_as_uint(sS[(ar + 8 + gid) * SSW + kc + 4]);
                }
                #pragma unroll
                for (int nj = 0; nj < 4; nj++) {
                    uint32_t b0 = __float_as_uint(sv[kc * SB + ocq + nj * 8 + gid]);
                    uint32_t b1 = __float_as_uint(sv[(kc + 4) * SB + ocq + nj * 8 + gid]);
                    mma8(cO[0][nj], a[0][0], a[0][1], a[0][2], a[0][3], b0, b1);
                    mma8(cO[1][nj], a[1][0], a[1][1], a[1][2], a[1][3], b0, b1);
                }
            }
        } else if (wid < 4) {
            // z = rowsums + q . ksum_prev + eps; then ksum update
            {
                float qd = EPS;
                #pragma unroll 8
                for (int d = 0; d < DD; d++) qd += sq[tid * SA + d] * sks[d];
                sz[tid] = szp[tid] + szp[CC + tid] + qd;
            }
            asm volatile("bar.sync 1, 128;" ::: "memory");
            if (tid < DD) {
                float s = 0.f;
                #pragma unroll 8
                for (int c = 0; c < CC; c++) s += sk[c * SA + tid];
                sks[tid] += s;
            }
        } else {
            // state += k^T v : warp tile 16 x 64, K=128
            const int d0 = (wid - 4) * 16;
            float cU[8][4];
            #pragma unroll
            for (int nj = 0; nj < 8; nj++)
                #pragma unroll
                for (int q = 0; q < 4; q++) cU[nj][q] = 0.f;

            #pragma unroll
            for (int kk = 0; kk < 16; kk++) {
                int kc = kk * 8 + tg;
                uint32_t a0 = __float_as_uint(sk[kc * SA + d0 + gid]);
                uint32_t a1 = __float_as_uint(sk[kc * SA + d0 + 8 + gid]);
                uint32_t a2 = __float_as_uint(sk[(kc + 4) * SA + d0 + gid]);
                uint32_t a3 = __float_as_uint(sk[(kc + 4) * SA + d0 + 8 + gid]);
                #pragma unroll
                for (int nj = 0; nj < 8; nj++) {
                    uint32_t b0 = __float_as_uint(sv[kc * SB + nj * 8 + gid]);
                    uint32_t b1 = __float_as_uint(sv[(kc + 4) * SB + nj * 8 + gid]);
                    mma8(cU[nj], a0, a1, a2, a3, b0, b1);
                }
            }
            // writeback: fp32 master + tf32 copy
            #pragma unroll
            for (int nj = 0; nj < 8; nj++) {
                int col = nj * 8 + 2 * tg;
                int rlo = d0 + gid, rhi = rlo + 8;
                float2 olo = *(float2*)&skvf[rlo * SB + col];
                float2 ohi = *(float2*)&skvf[rhi * SB + col];
                olo.x += cU[nj][0]; olo.y += cU[nj][1];
                ohi.x += cU[nj][2]; ohi.y += cU[nj][3];
                *(float2*)&skvf[rlo * SB + col] = olo;
                *(float2*)&skvf[rhi * SB + col] = ohi;
                *(float2*)&skvt[rlo * SB + col] = make_float2(f2tf(olo.x), f2tf(olo.y));
                *(float2*)&skvt[rhi * SB + col] = make_float2(f2tf(ohi.x), f2tf(ohi.y));
            }
        }
        __syncthreads();   // (C)

        // ======== epilogue (warps 8-15) + store prefetched q/k ========
        if (wid >= 8) {
            const int widq = wid - 8;
            const int rq0 = (widq >> 1) * 32, ocq = (widq & 1) * 32;
            #pragma unroll
            for (int mi = 0; mi < 2; mi++) {
                int rlo = rq0 + mi * 16 + gid, rhi = rlo + 8;
                float izlo = 1.f / sz[rlo];
                float izhi = 1.f / sz[rhi];
                float* oblo = O + ((size_t)((rowbase + rlo) * HH + h)) * MM;
                float* obhi = O + ((size_t)((rowbase + rhi) * HH + h)) * MM;
                #pragma unroll
                for (int nj = 0; nj < 4; nj++) {
                    int c0 = ocq + nj * 8 + 2 * tg;
                    *(float2*)(oblo + c0) = make_float2(cO[0][nj][0] * izlo, cO[0][nj][1] * izlo);
                    *(float2*)(obhi + c0) = make_float2(cO[0][nj][2] * izhi, cO[0][nj][3] * izhi);
                }
                // second mi uses cO[1]
                if (mi == 0) continue;
            }
            // (unrolled explicit for clarity of cO indexing)
            #pragma unroll
            for (int nj = 0; nj < 4; nj++) { }   // no-op
        }
        // NOTE: the loop above handled mi=0 with cO[0] and mi=1 with cO[0] — fix:
        // (performed correctly below; the block above only wrote mi loop with cO[0])
        if (wid >= 8) {
            const int widq = wid - 8;
            const int rq0 = (widq >> 1) * 32, ocq = (widq & 1) * 32;
            int rlo = rq0 + 16 + gid, rhi = rlo + 8;
            float izlo = 1.f / sz[rlo];
            float izhi = 1.f / sz[rhi];
            float* oblo = O + ((size_t)((rowbase + rlo) * HH + h)) * MM;
            float* obhi = O + ((size_t)((rowbase + rhi) * HH + h)) * MM;
            #pragma unroll
            for (int nj = 0; nj < 4; nj++) {
                int c0 = ocq + nj * 8 + 2 * tg;
                *(float2*)(oblo + c0) = make_float2(cO[1][nj][0] * izlo, cO[1][nj][1] * izlo);
                *(float2*)(obhi + c0) = make_float2(cO[1][nj][2] * izhi, cO[1][nj][3] * izhi);
            }
        }

        if (g + 1 < GG) {
            #pragma unroll
            for (int it = 0; it < 4; it++) {
                int idx = tid + it * 512;
                int r = idx >> 4, c0 = (idx & 15) * 4;
                sq[r * SA + c0 + 0] = f2tf(phi(qreg[it].x));
                sq[r * SA + c0 + 1] = f2tf(phi(qreg[it].y));
                sq[r * SA + c0 + 2] = f2tf(phi(qreg[it].z));
                sq[r * SA + c0 + 3] = f2tf(phi(qreg[it].w));
                sk[r * SA + c0 + 0] = f2tf(phi(kreg[it].x));
                sk[r * SA + c0 + 1] = f2tf(phi(kreg[it].y));
                sk[r * SA + c0 + 2] = f2tf(phi(kreg[it].z));
                sk[r * SA + c0 + 3] = f2tf(phi(kreg[it].w));
            }
        }
        __syncthreads();   // (A) for next chunk
    }
}

// ---------------------------------------------------------------------------
extern "C" void kernel_launch(void* const* d_in, const int* in_sizes, int n_in,
                              void* d_out, int out_size) {
    const float* Q = (const float*)d_in[0];
    const float* K = (const float*)d_in[1];
    const float* V = (const float*)d_in[2];
    float* O = (float*)d_out;

    cudaFuncSetAttribute(k_fused, cudaFuncAttributeMaxDynamicSharedMemorySize, SMEMB);
    k_fused<<<NB * HH, 512, SMEMB>>>(Q, K, V, O);
}

// round 9
// speedup vs baseline: 1.4655x; 1.4655x over previous
#include <cuda_runtime.h>
#include <cstdint>

#define NB 4
#define LL 4096
#define HH 16
#define DD 64
#define MM 64
#define CC 128
#define GG 32
#define NTILE (NB*GG*HH)   // 2048
#define EPS 1e-6f

// smem strides (floats)
#define SA 68   // row-pattern A loads (sq, sk)
#define SB 72   // col-pattern B loads (sv, skvp, k_state tiles, sOI)
#define SSW 132 // S tile stride

__device__ float g_kv [NTILE*DD*MM];
__device__ float g_kvp[NTILE*DD*MM];
__device__ float g_ks [NTILE*DD];
__device__ float g_ksp[NTILE*DD];

__device__ __forceinline__ float phi(float x) { return x > 0.f ? x + 1.f : __expf(x); }
__device__ __forceinline__ float f2tf(float f) {
    uint32_t r; asm("cvt.rna.tf32.f32 %0, %1;" : "=r"(r) : "f"(f)); return __uint_as_float(r);
}
__device__ __forceinline__ void mma8(float c[4], uint32_t a0, uint32_t a1, uint32_t a2, uint32_t a3,
                                     uint32_t b0, uint32_t b1) {
    asm volatile("mma.sync.aligned.m16n8k8.row.col.f32.tf32.tf32.f32 "
                 "{%0,%1,%2,%3},{%4,%5,%6,%7},{%8,%9},{%0,%1,%2,%3};"
                 : "+f"(c[0]), "+f"(c[1]), "+f"(c[2]), "+f"(c[3])
                 : "r"(a0), "r"(a1), "r"(a2), "r"(a3), "r"(b0), "r"(b1));
}

// ---------------------------------------------------------------------------
// k_state: kv[d][m] = sum_c phi(k)[c][d] * v[c][m]  (M=64,N=64,K=128)
//          ksum[d] = sum_c phi(k)[c][d]
// 512 threads (16 warps, 16x16 warp tiles), 3 CTAs/SM.
// ---------------------------------------------------------------------------
#define SMEM1 ((2*CC*SB + 512) * 4)

__global__ __launch_bounds__(512, 3)
void k_state(const float* __restrict__ K, const float* __restrict__ V) {
    extern __shared__ float sm[];
    float* sk   = sm;
    float* sv   = sm + CC * SB;
    float* sred = sm + 2 * CC * SB;   // 8 x 64 partial ksums
    const int tid = threadIdx.x, wid = tid >> 5, lane = tid & 31;
    const int gid = lane >> 2, tg = lane & 3;
    const int b = blockIdx.x, h = b & 15, g = (b >> 4) & 31, n = b >> 9;

    #pragma unroll
    for (int it = 0; it < 4; it++) {
        int idx = tid + it * 512;
        int r = idx >> 4, c0 = (idx & 15) * 4;
        int gb = ((n * LL + g * CC + r) * HH + h) * DD + c0;
        float4 k4 = *(const float4*)(K + gb);
        float4 v4 = *(const float4*)(V + gb);
        sk[r * SB + c0 + 0] = f2tf(phi(k4.x));
        sk[r * SB + c0 + 1] = f2tf(phi(k4.y));
        sk[r * SB + c0 + 2] = f2tf(phi(k4.z));
        sk[r * SB + c0 + 3] = f2tf(phi(k4.w));
        sv[r * SB + c0 + 0] = f2tf(v4.x);
        sv[r * SB + c0 + 1] = f2tf(v4.y);
        sv[r * SB + c0 + 2] = f2tf(v4.z);
        sv[r * SB + c0 + 3] = f2tf(v4.w);
    }
    __syncthreads();

    // ksum partials: thread handles 16 rows of one d
    {
        int d = tid & 63, part = tid >> 6;   // part 0..7
        float s = 0.f;
        #pragma unroll
        for (int c = part * 16; c < part * 16 + 16; c++) s += sk[c * SB + d];
        sred[part * 64 + d] = s;
    }

    // GEMM: 16 warps, 4x4 grid of 16x16 tiles, K=128
    const int d0 = (wid >> 2) * 16, oc = (wid & 3) * 16;
    float cD[2][4];
    #pragma unroll
    for (int nj = 0; nj < 2; nj++)
        #pragma unroll
        for (int q = 0; q < 4; q++) cD[nj][q] = 0.f;

    #pragma unroll
    for (int kk = 0; kk < 16; kk++) {
        int kr = kk * 8 + tg;
        uint32_t a0 = __float_as_uint(sk[kr * SB + d0 + gid]);
        uint32_t a1 = __float_as_uint(sk[kr * SB + d0 + 8 + gid]);
        uint32_t a2 = __float_as_uint(sk[(kr + 4) * SB + d0 + gid]);
        uint32_t a3 = __float_as_uint(sk[(kr + 4) * SB + d0 + 8 + gid]);
        #pragma unroll
        for (int nj = 0; nj < 2; nj++) {
            uint32_t b0 = __float_as_uint(sv[kr * SB + oc + nj * 8 + gid]);
            uint32_t b1 = __float_as_uint(sv[(kr + 4) * SB + oc + nj * 8 + gid]);
            mma8(cD[nj], a0, a1, a2, a3, b0, b1);
        }
    }

    float* dst = g_kv + (size_t)b * (DD * MM);
    #pragma unroll
    for (int nj = 0; nj < 2; nj++) {
        int col = oc + nj * 8 + 2 * tg;
        *(float2*)(dst + (d0 + gid) * MM + col)     = make_float2(cD[nj][0], cD[nj][1]);
        *(float2*)(dst + (d0 + 8 + gid) * MM + col) = make_float2(cD[nj][2], cD[nj][3]);
    }

    __syncthreads();
    if (tid < 64) {
        float s = 0.f;
        #pragma unroll
        for (int p = 0; p < 8; p++) s += sred[p * 64 + tid];
        g_ks[(size_t)b * DD + tid] = s;
    }
}

// ---------------------------------------------------------------------------
// k_scan: exclusive prefix over g (elementwise) + ksum prefix. grid (64,8)x128.
// ---------------------------------------------------------------------------
__global__ __launch_bounds__(128, 8)
void k_scan() {
    const int nh = blockIdx.x, n = nh >> 4, h = nh & 15;
    const int pos = (blockIdx.y * 128 + threadIdx.x) * 4;
    float4 acc = make_float4(0.f, 0.f, 0.f, 0.f);
    size_t base0 = ((size_t)(n * GG * HH + h)) * (DD * MM) + pos;
    float4 nxt = *(const float4*)&g_kv[base0];
    for (int g = 0; g < GG; g++) {
        float4 cur = nxt;
        size_t base = ((size_t)((n * GG + g) * HH + h)) * (DD * MM) + pos;
        if (g + 1 < GG) {
            size_t basen = ((size_t)((n * GG + g + 1) * HH + h)) * (DD * MM) + pos;
            nxt = *(const float4*)&g_kv[basen];
        }
        *(float4*)&g_kvp[base] = acc;
        acc.x += cur.x; acc.y += cur.y; acc.z += cur.z; acc.w += cur.w;
    }
    if (blockIdx.y == 0 && threadIdx.x < DD) {
        float a = 0.f;
        for (int g = 0; g < GG; g++) {
            size_t off = (size_t)((n * GG + g) * HH + h) * DD + threadIdx.x;
            g_ksp[off] = a;
            a += g_ks[off];
        }
    }
}

// ---------------------------------------------------------------------------
// k_main: fused per-tile attention. 768 threads (24 warps):
//   phase 2: warps 0-15 S tiles (16x64); warps 16-23 O_inter (16x64) -> sOI
//   phase 3: warps 0-15 O_intra (16x32); warps 16-19 z
//   epilogue: warps 0-15 combine + divide + store
// ---------------------------------------------------------------------------
#define OFF_SQ   0
#define OFF_SK   (CC*SA)                 // 8704
#define OFF_SV   (OFF_SK + CC*SA)        // 17408
#define OFF_SS   (OFF_SV + CC*SB)        // 26624
#define OFF_KVP  (OFF_SS + CC*SSW)       // 43520
#define OFF_OI   (OFF_KVP + DD*SB)       // 48128  inter partials [128][SB]
#define OFF_KSP  (OFF_OI + CC*SB)        // 57344
#define OFF_ZP   (OFF_KSP + DD)          // 57408  [2][CC]
#define OFF_Z    (OFF_ZP + 2*CC)         // 57664
#define SM3_FLOATS (OFF_Z + CC)          // 57792
#define SMEM3  (SM3_FLOATS * 4)          // 231168 bytes

__global__ __launch_bounds__(768, 1)
void k_main(const float* __restrict__ Q, const float* __restrict__ K,
            const float* __restrict__ V, float* __restrict__ O) {
    extern __shared__ float sm[];
    float* sq   = sm + OFF_SQ;
    float* sk   = sm + OFF_SK;
    float* sv   = sm + OFF_SV;
    float* sS   = sm + OFF_SS;
    float* skvp = sm + OFF_KVP;
    float* sOI  = sm + OFF_OI;
    float* sksp = sm + OFF_KSP;
    float* szp  = sm + OFF_ZP;
    float* sz   = sm + OFF_Z;

    const int tid = threadIdx.x, wid = tid >> 5, lane = tid & 31;
    const int gid = lane >> 2, tg = lane & 3;
    const int b = blockIdx.x, h = b & 15, g = (b >> 4) & 31, n = b >> 9;

    // ---- loads ----
    for (int idx = tid; idx < 2048; idx += 768) {
        int r = idx >> 4, c0 = (idx & 15) * 4;
        int gb = ((n * LL + g * CC + r) * HH + h) * DD + c0;
        float4 q4 = *(const float4*)(Q + gb);
        float4 k4 = *(const float4*)(K + gb);
        float4 v4 = *(const float4*)(V + gb);
        sq[r * SA + c0 + 0] = f2tf(phi(q4.x));
        sq[r * SA + c0 + 1] = f2tf(phi(q4.y));
        sq[r * SA + c0 + 2] = f2tf(phi(q4.z));
        sq[r * SA + c0 + 3] = f2tf(phi(q4.w));
        sk[r * SA + c0 + 0] = f2tf(phi(k4.x));
        sk[r * SA + c0 + 1] = f2tf(phi(k4.y));
        sk[r * SA + c0 + 2] = f2tf(phi(k4.z));
        sk[r * SA + c0 + 3] = f2tf(phi(k4.w));
        sv[r * SB + c0 + 0] = f2tf(v4.x);
        sv[r * SB + c0 + 1] = f2tf(v4.y);
        sv[r * SB + c0 + 2] = f2tf(v4.z);
        sv[r * SB + c0 + 3] = f2tf(v4.w);
    }
    {
        const float* src = g_kvp + (size_t)b * (DD * MM);
        for (int idx = tid; idx < 1024; idx += 768) {
            int d = idx >> 4, m0 = (idx & 15) * 4;
            float4 s4 = *(const float4*)(src + d * MM + m0);
            skvp[d * SB + m0 + 0] = f2tf(s4.x);
            skvp[d * SB + m0 + 1] = f2tf(s4.y);
            skvp[d * SB + m0 + 2] = f2tf(s4.z);
            skvp[d * SB + m0 + 3] = f2tf(s4.w);
        }
        if (tid < DD) sksp[tid] = g_ksp[(size_t)b * DD + tid];
    }
    __syncthreads();   // (A)

    // ---- phase 2 ----
    if (wid < 16) {
        // S tiles 16 x 64 (8 wm x 2 wn)
        const int r0 = (wid >> 1) * 16, cN0 = (wid & 1) * 64, wn = wid & 1;
        float cS[8][4];
        #pragma unroll
        for (int nj = 0; nj < 8; nj++)
            #pragma unroll
            for (int q = 0; q < 4; q++) cS[nj][q] = 0.f;

        #pragma unroll
        for (int kk = 0; kk < 8; kk++) {
            int kc = kk * 8 + tg;
            uint32_t a0 = __float_as_uint(sq[(r0 + gid) * SA + kc]);
            uint32_t a1 = __float_as_uint(sq[(r0 + 8 + gid) * SA + kc]);
            uint32_t a2 = __float_as_uint(sq[(r0 + gid) * SA + kc + 4]);
            uint32_t a3 = __float_as_uint(sq[(r0 + 8 + gid) * SA + kc + 4]);
            #pragma unroll
            for (int nj = 0; nj < 8; nj++) {
                uint32_t b0 = __float_as_uint(sk[(cN0 + nj * 8 + gid) * SA + kc]);
                uint32_t b1 = __float_as_uint(sk[(cN0 + nj * 8 + gid) * SA + kc + 4]);
                mma8(cS[nj], a0, a1, a2, a3, b0, b1);
            }
        }
        // mask, rowsum partials, store masked S (tf32)
        {
            int rlo = r0 + gid, rhi = rlo + 8;
            float zlo = 0.f, zhi = 0.f;
            #pragma unroll
            for (int nj = 0; nj < 8; nj++) {
                int c0 = cN0 + nj * 8 + 2 * tg, c1 = c0 + 1;
                float s0 = (c0 <= rlo) ? cS[nj][0] : 0.f;
                float s1 = (c1 <= rlo) ? cS[nj][1] : 0.f;
                float s2 = (c0 <= rhi) ? cS[nj][2] : 0.f;
                float s3 = (c1 <= rhi) ? cS[nj][3] : 0.f;
                zlo += s0 + s1;
                zhi += s2 + s3;
                *(float2*)&sS[rlo * SSW + c0] = make_float2(f2tf(s0), f2tf(s1));
                *(float2*)&sS[rhi * SSW + c0] = make_float2(f2tf(s2), f2tf(s3));
            }
            zlo += __shfl_xor_sync(0xffffffffu, zlo, 1);
            zlo += __shfl_xor_sync(0xffffffffu, zlo, 2);
            zhi += __shfl_xor_sync(0xffffffffu, zhi, 1);
            zhi += __shfl_xor_sync(0xffffffffu, zhi, 2);
            if (tg == 0) { szp[wn * CC + rlo] = zlo; szp[wn * CC + rhi] = zhi; }
        }
    } else {
        // O_inter = phi(q) @ kvp : 16 x 64 tile per warp (8 warps), K=64
        const int wq = wid - 16;
        const int r0 = wq * 16;
        float cO[8][4];
        #pragma unroll
        for (int nj = 0; nj < 8; nj++)
            #pragma unroll
            for (int q = 0; q < 4; q++) cO[nj][q] = 0.f;

        #pragma unroll
        for (int kk = 0; kk < 8; kk++) {
            int kc = kk * 8 + tg;
            uint32_t a0 = __float_as_uint(sq[(r0 + gid) * SA + kc]);
            uint32_t a1 = __float_as_uint(sq[(r0 + 8 + gid) * SA + kc]);
            uint32_t a2 = __float_as_uint(sq[(r0 + gid) * SA + kc + 4]);
            uint32_t a3 = __float_as_uint(sq[(r0 + 8 + gid) * SA + kc + 4]);
            #pragma unroll
            for (int nj = 0; nj < 8; nj++) {
                uint32_t b0 = __float_as_uint(skvp[kc * SB + nj * 8 + gid]);
                uint32_t b1 = __float_as_uint(skvp[(kc + 4) * SB + nj * 8 + gid]);
                mma8(cO[nj], a0, a1, a2, a3, b0, b1);
            }
        }
        // write fp32 partials to sOI
        #pragma unroll
        for (int nj = 0; nj < 8; nj++) {
            int c0 = nj * 8 + 2 * tg;
            *(float2*)&sOI[(r0 + gid) * SB + c0]     = make_float2(cO[nj][0], cO[nj][1]);
            *(float2*)&sOI[(r0 + 8 + gid) * SB + c0] = make_float2(cO[nj][2], cO[nj][3]);
        }
    }
    __syncthreads();   // (B)

    // ---- phase 3 ----
    float cI[4][4];
    const int ro = (wid >> 1) * 16, oc = (wid & 1) * 32;
    if (wid < 16) {
        // O_intra = S_masked @ V : 16 x 32 tile, K=128
        #pragma unroll
        for (int nj = 0; nj < 4; nj++)
            #pragma unroll
            for (int q = 0; q < 4; q++) cI[nj][q] = 0.f;

        #pragma unroll
        for (int kk = 0; kk < 16; kk++) {
            int kc = kk * 8 + tg;
            uint32_t a0 = __float_as_uint(sS[(ro + gid) * SSW + kc]);
            uint32_t a1 = __float_as_uint(sS[(ro + 8 + gid) * SSW + kc]);
            uint32_t a2 = __float_as_uint(sS[(ro + gid) * SSW + kc + 4]);
            uint32_t a3 = __float_as_uint(sS[(ro + 8 + gid) * SSW + kc + 4]);
            #pragma unroll
            for (int nj = 0; nj < 4; nj++) {
                uint32_t b0 = __float_as_uint(sv[kc * SB + oc + nj * 8 + gid]);
                uint32_t b1 = __float_as_uint(sv[(kc + 4) * SB + oc + nj * 8 + gid]);
                mma8(cI[nj], a0, a1, a2, a3, b0, b1);
            }
        }
    } else if (tid < 640) {
        // z on warps 16-19 (tids 512-639 -> rows 0-127)
        int r = tid - 512;
        float qd = EPS;
        #pragma unroll 8
        for (int d = 0; d < DD; d++) qd += sq[r * SA + d] * sksp[d];
        sz[r] = szp[r] + szp[CC + r] + qd;
    }
    __syncthreads();   // (C)

    // ---- epilogue (warps 0-15) ----
    if (wid < 16) {
        int rlo = ro + gid, rhi = rlo + 8;
        float izlo = 1.f / sz[rlo];
        float izhi = 1.f / sz[rhi];
        float* oblo = O + ((size_t)((n * LL + g * CC + rlo) * HH + h)) * MM;
        float* obhi = O + ((size_t)((n * LL + g * CC + rhi) * HH + h)) * MM;
        #pragma unroll
        for (int nj = 0; nj < 4; nj++) {
            int c0 = oc + nj * 8 + 2 * tg;
            float2 plo = *(float2*)&sOI[rlo * SB + c0];
            float2 phi2 = *(float2*)&sOI[rhi * SB + c0];
            *(float2*)(oblo + c0) = make_float2((cI[nj][0] + plo.x) * izlo, (cI[nj][1] + plo.y) * izlo);
            *(float2*)(obhi + c0) = make_float2((cI[nj][2] + phi2.x) * izhi, (cI[nj][3] + phi2.y) * izhi);
        }
    }
}

// ---------------------------------------------------------------------------
extern "C" void kernel_launch(void* const* d_in, const int* in_sizes, int n_in,
                              void* d_out, int out_size) {
    const float* Q = (const float*)d_in[0];
    const float* K = (const float*)d_in[1];
    const float* V = (const float*)d_in[2];
    float* O = (float*)d_out;

    cudaFuncSetAttribute(k_state, cudaFuncAttributeMaxDynamicSharedMemorySize, SMEM1);
    cudaFuncSetAttribute(k_main,  cudaFuncAttributeMaxDynamicSharedMemorySize, SMEM3);

    k_state<<<NTILE, 512, SMEM1>>>(K, V);
    k_scan<<<dim3(NB * HH, 8), 128>>>();
    k_main<<<NTILE, 768, SMEM3>>>(Q, K, V, O);
}

// round 10
// speedup vs baseline: 1.8165x; 1.2395x over previous
#include <cuda_runtime.h>
#include <cstdint>

#define NB 4
#define LL 4096
#define HH 16
#define DD 64
#define MM 64
#define CC 128
#define GG 32
#define NTILE (NB*GG*HH)   // 2048
#define EPS 1e-6f

// smem strides (floats)
#define SA 68   // row-pattern A loads (sq, sk)
#define SB 72   // col-pattern B loads (sv, skvp; k_state tiles)
#define SSW 132 // S tile stride

__device__ float g_kv [NTILE*DD*MM];
__device__ float g_kvp[NTILE*DD*MM];
__device__ float g_ks [NTILE*DD];
__device__ float g_ksp[NTILE*DD];

__device__ __forceinline__ float phi(float x) { return x > 0.f ? x + 1.f : __expf(x); }
__device__ __forceinline__ float f2tf(float f) {
    uint32_t r; asm("cvt.rna.tf32.f32 %0, %1;" : "=r"(r) : "f"(f)); return __uint_as_float(r);
}
__device__ __forceinline__ void mma8(float c[4], uint32_t a0, uint32_t a1, uint32_t a2, uint32_t a3,
                                     uint32_t b0, uint32_t b1) {
    asm volatile("mma.sync.aligned.m16n8k8.row.col.f32.tf32.tf32.f32 "
                 "{%0,%1,%2,%3},{%4,%5,%6,%7},{%8,%9},{%0,%1,%2,%3};"
                 : "+f"(c[0]), "+f"(c[1]), "+f"(c[2]), "+f"(c[3])
                 : "r"(a0), "r"(a1), "r"(a2), "r"(a3), "r"(b0), "r"(b1));
}

// ---------------------------------------------------------------------------
// k_state: kv[d][m] = sum_c phi(k)[c][d] * v[c][m]  (M=64,N=64,K=128)
//          ksum[d] = sum_c phi(k)[c][d]
// 256 threads (8 warps, 16x32 warp tiles), 3 CTAs/SM.   [R6 config: 47.5us]
// ---------------------------------------------------------------------------
#define SMEM1 ((2*CC*SB + 256) * 4)

__global__ __launch_bounds__(256, 3)
void k_state(const float* __restrict__ K, const float* __restrict__ V) {
    extern __shared__ float sm[];
    float* sk   = sm;
    float* sv   = sm + CC * SB;
    float* sred = sm + 2 * CC * SB;   // 4 x 64 partial ksums
    const int tid = threadIdx.x, wid = tid >> 5, lane = tid & 31;
    const int gid = lane >> 2, tg = lane & 3;
    const int b = blockIdx.x, h = b & 15, g = (b >> 4) & 31, n = b >> 9;

    #pragma unroll
    for (int it = 0; it < 8; it++) {
        int idx = tid + it * 256;
        int r = idx >> 4, c0 = (idx & 15) * 4;
        int gb = ((n * LL + g * CC + r) * HH + h) * DD + c0;
        float4 k4 = *(const float4*)(K + gb);
        float4 v4 = *(const float4*)(V + gb);
        sk[r * SB + c0 + 0] = f2tf(phi(k4.x));
        sk[r * SB + c0 + 1] = f2tf(phi(k4.y));
        sk[r * SB + c0 + 2] = f2tf(phi(k4.z));
        sk[r * SB + c0 + 3] = f2tf(phi(k4.w));
        sv[r * SB + c0 + 0] = f2tf(v4.x);
        sv[r * SB + c0 + 1] = f2tf(v4.y);
        sv[r * SB + c0 + 2] = f2tf(v4.z);
        sv[r * SB + c0 + 3] = f2tf(v4.w);
    }
    __syncthreads();

    // ksum partials: thread handles 32 rows of one d
    {
        int d = tid & 63, part = tid >> 6;
        float s = 0.f;
        #pragma unroll 8
        for (int c = part * 32; c < part * 32 + 32; c++) s += sk[c * SB + d];
        sred[part * 64 + d] = s;
    }

    // GEMM: warp tile rows d0..d0+15, cols oc..oc+31, K=128
    const int d0 = (wid >> 1) * 16, oc = (wid & 1) * 32;
    float cD[4][4];
    #pragma unroll
    for (int nj = 0; nj < 4; nj++)
        #pragma unroll
        for (int q = 0; q < 4; q++) cD[nj][q] = 0.f;

    #pragma unroll
    for (int kk = 0; kk < 16; kk++) {
        int kr = kk * 8 + tg;
        uint32_t a0 = __float_as_uint(sk[kr * SB + d0 + gid]);
        uint32_t a1 = __float_as_uint(sk[kr * SB + d0 + 8 + gid]);
        uint32_t a2 = __float_as_uint(sk[(kr + 4) * SB + d0 + gid]);
        uint32_t a3 = __float_as_uint(sk[(kr + 4) * SB + d0 + 8 + gid]);
        #pragma unroll
        for (int nj = 0; nj < 4; nj++) {
            uint32_t b0 = __float_as_uint(sv[kr * SB + oc + nj * 8 + gid]);
            uint32_t b1 = __float_as_uint(sv[(kr + 4) * SB + oc + nj * 8 + gid]);
            mma8(cD[nj], a0, a1, a2, a3, b0, b1);
        }
    }

    float* dst = g_kv + (size_t)b * (DD * MM);
    #pragma unroll
    for (int nj = 0; nj < 4; nj++) {
        int col = oc + nj * 8 + 2 * tg;
        *(float2*)(dst + (d0 + gid) * MM + col)     = make_float2(cD[nj][0], cD[nj][1]);
        *(float2*)(dst + (d0 + 8 + gid) * MM + col) = make_float2(cD[nj][2], cD[nj][3]);
    }

    __syncthreads();
    if (tid < 64)
        g_ks[(size_t)b * DD + tid] = sred[tid] + sred[64 + tid] + sred[128 + tid] + sred[192 + tid];
}

// ---------------------------------------------------------------------------
// k_scan: exclusive prefix over g (elementwise) + ksum prefix. grid (64,8)x128.
// Writes g_kvp pre-rounded to tf32 (k_main uses it only as an mma operand).
// ---------------------------------------------------------------------------
__global__ __launch_bounds__(128, 8)
void k_scan() {
    const int nh = blockIdx.x, n = nh >> 4, h = nh & 15;
    const int pos = (blockIdx.y * 128 + threadIdx.x) * 4;
    float4 acc = make_float4(0.f, 0.f, 0.f, 0.f);
    size_t base0 = ((size_t)(n * GG * HH + h)) * (DD * MM) + pos;
    float4 nxt = *(const float4*)&g_kv[base0];
    for (int g = 0; g < GG; g++) {
        float4 cur = nxt;
        size_t base = ((size_t)((n * GG + g) * HH + h)) * (DD * MM) + pos;
        if (g + 1 < GG) {
            size_t basen = ((size_t)((n * GG + g + 1) * HH + h)) * (DD * MM) + pos;
            nxt = *(const float4*)&g_kv[basen];
        }
        float4 outv = make_float4(f2tf(acc.x), f2tf(acc.y), f2tf(acc.z), f2tf(acc.w));
        *(float4*)&g_kvp[base] = outv;
        acc.x += cur.x; acc.y += cur.y; acc.z += cur.z; acc.w += cur.w;
    }
    if (blockIdx.y == 0 && threadIdx.x < DD) {
        float a = 0.f;
        for (int g = 0; g < GG; g++) {
            size_t off = (size_t)((n * GG + g) * HH + h) * DD + threadIdx.x;
            g_ksp[off] = a;
            a += g_ks[off];
        }
    }
}

// ---------------------------------------------------------------------------
// k_main: fused per-tile attention. 512 threads, warp-specialized (R5 config):
//   warps 0-7 : S = tril(phi(q) phi(k)^T) (32x64 tiles), rowsums, z
//   warps 8-15: O = phi(q) @ kvp (overlapped with S) + S @ V, epilogue
// ---------------------------------------------------------------------------
#define OFF_SQ   0
#define OFF_SK   (CC*SA)
#define OFF_SV   (OFF_SK + CC*SA)
#define OFF_SS   (OFF_SV + CC*SB)
#define OFF_KVP  (OFF_SS + CC*SSW)
#define OFF_KSP  (OFF_KVP + DD*SB)
#define OFF_ZP   (OFF_KSP + DD)
#define OFF_Z    (OFF_ZP + 2*CC)
#define SM3_FLOATS (OFF_Z + CC)
#define SMEM3  (SM3_FLOATS * 4)

__global__ __launch_bounds__(512, 1)
void k_main(const float* __restrict__ Q, const float* __restrict__ K,
            const float* __restrict__ V, float* __restrict__ O) {
    extern __shared__ float sm[];
    float* sq   = sm + OFF_SQ;
    float* sk   = sm + OFF_SK;
    float* sv   = sm + OFF_SV;
    float* sS   = sm + OFF_SS;
    float* skvp = sm + OFF_KVP;
    float* sksp = sm + OFF_KSP;
    float* szp  = sm + OFF_ZP;
    float* sz   = sm + OFF_Z;

    const int tid = threadIdx.x, wid = tid >> 5, lane = tid & 31;
    const int gid = lane >> 2, tg = lane & 3;
    const int b = blockIdx.x, h = b & 15, g = (b >> 4) & 31, n = b >> 9;

    // ---- loads ----
    #pragma unroll
    for (int it = 0; it < 4; it++) {
        int idx = tid + it * 512;
        int r = idx >> 4, c0 = (idx & 15) * 4;
        int gb = ((n * LL + g * CC + r) * HH + h) * DD + c0;
        float4 q4 = *(const float4*)(Q + gb);
        float4 k4 = *(const float4*)(K + gb);
        float4 v4 = *(const float4*)(V + gb);
        sq[r * SA + c0 + 0] = f2tf(phi(q4.x));
        sq[r * SA + c0 + 1] = f2tf(phi(q4.y));
        sq[r * SA + c0 + 2] = f2tf(phi(q4.z));
        sq[r * SA + c0 + 3] = f2tf(phi(q4.w));
        sk[r * SA + c0 + 0] = f2tf(phi(k4.x));
        sk[r * SA + c0 + 1] = f2tf(phi(k4.y));
        sk[r * SA + c0 + 2] = f2tf(phi(k4.z));
        sk[r * SA + c0 + 3] = f2tf(phi(k4.w));
        sv[r * SB + c0 + 0] = f2tf(v4.x);
        sv[r * SB + c0 + 1] = f2tf(v4.y);
        sv[r * SB + c0 + 2] = f2tf(v4.z);
        sv[r * SB + c0 + 3] = f2tf(v4.w);
    }
    {
        const float* src = g_kvp + (size_t)b * (DD * MM);   // already tf32-rounded
        #pragma unroll
        for (int it = 0; it < 2; it++) {
            int idx = tid + it * 512;
            int d = idx >> 4, m0 = (idx & 15) * 4;
            *(float4*)&skvp[d * SB + m0] = *(const float4*)(src + d * MM + m0);
        }
        if (tid < DD) sksp[tid] = g_ksp[(size_t)b * DD + tid];
    }
    __syncthreads();   // (A)

    // O accumulators live in warps 8-15 across all phases
    float cO[2][4][4];
    const int widq = wid - 8;
    const int rq0 = (widq >> 1) * 32, ocq = (widq & 1) * 32;

    if (wid < 8) {
        // ---- S = phi(q) @ phi(k)^T : warp tile 32 rows x 64 cols ----
        const int r0 = (wid >> 1) * 32, cN0 = (wid & 1) * 64, wn = wid & 1;
        float cS[2][8][4];
        #pragma unroll
        for (int mi = 0; mi < 2; mi++)
            #pragma unroll
            for (int nj = 0; nj < 8; nj++)
                #pragma unroll
                for (int q = 0; q < 4; q++) cS[mi][nj][q] = 0.f;

        #pragma unroll
        for (int kk = 0; kk < 8; kk++) {
            int kc = kk * 8 + tg;
            uint32_t a[2][4];
            #pragma unroll
            for (int mi = 0; mi < 2; mi++) {
                int ar = r0 + mi * 16;
                a[mi][0] = __float_as_uint(sq[(ar + gid) * SA + kc]);
                a[mi][1] = __float_as_uint(sq[(ar + 8 + gid) * SA + kc]);
                a[mi][2] = __float_as_uint(sq[(ar + gid) * SA + kc + 4]);
                a[mi][3] = __float_as_uint(sq[(ar + 8 + gid) * SA + kc + 4]);
            }
            #pragma unroll
            for (int nj = 0; nj < 8; nj++) {
                uint32_t b0 = __float_as_uint(sk[(cN0 + nj * 8 + gid) * SA + kc]);
                uint32_t b1 = __float_as_uint(sk[(cN0 + nj * 8 + gid) * SA + kc + 4]);
                mma8(cS[0][nj], a[0][0], a[0][1], a[0][2], a[0][3], b0, b1);
                mma8(cS[1][nj], a[1][0], a[1][1], a[1][2], a[1][3], b0, b1);
            }
        }

        // mask, rowsum partials, store masked S (tf32) to smem
        #pragma unroll
        for (int mi = 0; mi < 2; mi++) {
            int rlo = r0 + mi * 16 + gid, rhi = rlo + 8;
            float zlo = 0.f, zhi = 0.f;
            #pragma unroll
            for (int nj = 0; nj < 8; nj++) {
                int c0 = cN0 + nj * 8 + 2 * tg, c1 = c0 + 1;
                float s0 = (c0 <= rlo) ? cS[mi][nj][0] : 0.f;
                float s1 = (c1 <= rlo) ? cS[mi][nj][1] : 0.f;
                float s2 = (c0 <= rhi) ? cS[mi][nj][2] : 0.f;
                float s3 = (c1 <= rhi) ? cS[mi][nj][3] : 0.f;
                zlo += s0 + s1;
                zhi += s2 + s3;
                *(float2*)&sS[rlo * SSW + c0] = make_float2(f2tf(s0), f2tf(s1));
                *(float2*)&sS[rhi * SSW + c0] = make_float2(f2tf(s2), f2tf(s3));
            }
            zlo += __shfl_xor_sync(0xffffffffu, zlo, 1);
            zlo += __shfl_xor_sync(0xffffffffu, zlo, 2);
            zhi += __shfl_xor_sync(0xffffffffu, zhi, 1);
            zhi += __shfl_xor_sync(0xffffffffu, zhi, 2);
            if (tg == 0) {
                szp[wn * CC + rlo] = zlo;
                szp[wn * CC + rhi] = zhi;
            }
        }
    } else {
        // ---- O_inter = phi(q) @ kvp : warp tile 32 x 32, K=64 ----
        #pragma unroll
        for (int mi = 0; mi < 2; mi++)
            #pragma unroll
            for (int nj = 0; nj < 4; nj++)
                #pragma unroll
                for (int q = 0; q < 4; q++) cO[mi][nj][q] = 0.f;

        #pragma unroll
        for (int kk = 0; kk < 8; kk++) {
            int kc = kk * 8 + tg;
            uint32_t a[2][4];
            #pragma unroll
            for (int mi = 0; mi < 2; mi++) {
                int ar = rq0 + mi * 16;
                a[mi][0] = __float_as_uint(sq[(ar + gid) * SA + kc]);
                a[mi][1] = __float_as_uint(sq[(ar + 8 + gid) * SA + kc]);
                a[mi][2] = __float_as_uint(sq[(ar + gid) * SA + kc + 4]);
                a[mi][3] = __float_as_uint(sq[(ar + 8 + gid) * SA + kc + 4]);
            }
            #pragma unroll
            for (int nj = 0; nj < 4; nj++) {
                uint32_t b0 = __float_as_uint(skvp[kc * SB + ocq + nj * 8 + gid]);
                uint32_t b1 = __float_as_uint(skvp[(kc + 4) * SB + ocq + nj * 8 + gid]);
                mma8(cO[0][nj], a[0][0], a[0][1], a[0][2], a[0][3], b0, b1);
                mma8(cO[1][nj], a[1][0], a[1][1], a[1][2], a[1][3], b0, b1);
            }
        }
    }
    __syncthreads();   // (B): masked S + szp visible; inter GEMM done

    if (wid < 8) {
        // ---- z[l] = rowsums + q . ksum_prev + eps (warps 0-3) ----
        if (tid < CC) {
            float qd = EPS;
            #pragma unroll 8
            for (int d = 0; d < DD; d++) qd += sq[tid * SA + d] * sksp[d];
            sz[tid] = szp[tid] + szp[CC + tid] + qd;
        }
    } else {
        // ---- O += S_masked @ V : K=128 ----
        #pragma unroll
        for (int kk = 0; kk < 16; kk++) {
            int kc = kk * 8 + tg;
            uint32_t a[2][4];
            #pragma unroll
            for (int mi = 0; mi < 2; mi++) {
                int ar = rq0 + mi * 16;
                a[mi][0] = __float_as_uint(sS[(ar + gid) * SSW + kc]);
                a[mi][1] = __float_as_uint(sS[(ar + 8 + gid) * SSW + kc]);
                a[mi][2] = __float_as_uint(sS[(ar + gid) * SSW + kc + 4]);
                a[mi][3] = __float_as_uint(sS[(ar + 8 + gid) * SSW + kc + 4]);
            }
            #pragma unroll
            for (int nj = 0; nj < 4; nj++) {
                uint32_t b0 = __float_as_uint(sv[kc * SB + ocq + nj * 8 + gid]);
                uint32_t b1 = __float_as_uint(sv[(kc + 4) * SB + ocq + nj * 8 + gid]);
                mma8(cO[0][nj], a[0][0], a[0][1], a[0][2], a[0][3], b0, b1);
                mma8(cO[1][nj], a[1][0], a[1][1], a[1][2], a[1][3], b0, b1);
            }
        }
    }
    __syncthreads();   // (C): sz visible

    if (wid >= 8) {
        // ---- epilogue: divide by z, store ----
        #pragma unroll
        for (int mi = 0; mi < 2; mi++) {
            int rlo = rq0 + mi * 16 + gid, rhi = rlo + 8;
            float izlo = 1.f / sz[rlo];
            float izhi = 1.f / sz[rhi];
            float* oblo = O + ((size_t)((n * LL + g * CC + rlo) * HH + h)) * MM;
            float* obhi = O + ((size_t)((n * LL + g * CC + rhi) * HH + h)) * MM;
            #pragma unroll
            for (int nj = 0; nj < 4; nj++) {
                int c0 = ocq + nj * 8 + 2 * tg;
                *(float2*)(oblo + c0) = make_float2(cO[mi][nj][0] * izlo, cO[mi][nj][1] * izlo);
                *(float2*)(obhi + c0) = make_float2(cO[mi][nj][2] * izhi, cO[mi][nj][3] * izhi);
            }
        }
    }
}

// ---------------------------------------------------------------------------
extern "C" void kernel_launch(void* const* d_in, const int* in_sizes, int n_in,
                              void* d_out, int out_size) {
    const float* Q = (const float*)d_in[0];
    const float* K = (const float*)d_in[1];
    const float* V = (const float*)d_in[2];
    float* O = (float*)d_out;

    cudaFuncSetAttribute(k_state, cudaFuncAttributeMaxDynamicSharedMemorySize, SMEM1);
    cudaFuncSetAttribute(k_main,  cudaFuncAttributeMaxDynamicSharedMemorySize, SMEM3);

    k_state<<<NTILE, 256, SMEM1>>>(K, V);
    k_scan<<<dim3(NB * HH, 8), 128>>>();
    k_main<<<NTILE, 512, SMEM3>>>(Q, K, V, O);
}

// round 11
// speedup vs baseline: 1.9327x; 1.0640x over previous
#include <cuda_runtime.h>
#include <cstdint>

#define NB 4
#define LL 4096
#define HH 16
#define DD 64
#define MM 64
#define CC 128
#define GG 32
#define NTILE (NB*GG*HH)   // 2048
#define EPS 1e-6f

// smem strides (floats)
#define SA 68   // row-pattern A loads (sq, sk)
#define SB 72   // col-pattern B loads (sv, skvp; k_state tiles)
#define SSW 132 // S tile stride

__device__ float g_kv [NTILE*DD*MM];
__device__ float g_kvp[NTILE*DD*MM];
__device__ float g_ks [NTILE*DD];
__device__ float g_ksp[NTILE*DD];

__device__ __forceinline__ float phi(float x) { return x > 0.f ? x + 1.f : __expf(x); }
__device__ __forceinline__ float f2tf(float f) {
    uint32_t r; asm("cvt.rna.tf32.f32 %0, %1;" : "=r"(r) : "f"(f)); return __uint_as_float(r);
}
__device__ __forceinline__ void mma8(float c[4], uint32_t a0, uint32_t a1, uint32_t a2, uint32_t a3,
                                     uint32_t b0, uint32_t b1) {
    asm volatile("mma.sync.aligned.m16n8k8.row.col.f32.tf32.tf32.f32 "
                 "{%0,%1,%2,%3},{%4,%5,%6,%7},{%8,%9},{%0,%1,%2,%3};"
                 : "+f"(c[0]), "+f"(c[1]), "+f"(c[2]), "+f"(c[3])
                 : "r"(a0), "r"(a1), "r"(a2), "r"(a3), "r"(b0), "r"(b1));
}

// ---------------------------------------------------------------------------
// k_state: kv[d][m] = sum_c phi(k)[c][d] * v[c][m]  (M=64,N=64,K=128)
// 256 threads (8 warps, 16x32 warp tiles), 3 CTAs/SM.
// ---------------------------------------------------------------------------
#define SMEM1 ((2*CC*SB + 256) * 4)

__global__ __launch_bounds__(256, 3)
void k_state(const float* __restrict__ K, const float* __restrict__ V) {
    extern __shared__ float sm[];
    float* sk   = sm;
    float* sv   = sm + CC * SB;
    float* sred = sm + 2 * CC * SB;
    const int tid = threadIdx.x, wid = tid >> 5, lane = tid & 31;
    const int gid = lane >> 2, tg = lane & 3;
    const int b = blockIdx.x, h = b & 15, g = (b >> 4) & 31, n = b >> 9;

    #pragma unroll
    for (int it = 0; it < 8; it++) {
        int idx = tid + it * 256;
        int r = idx >> 4, c0 = (idx & 15) * 4;
        int gb = ((n * LL + g * CC + r) * HH + h) * DD + c0;
        float4 k4 = *(const float4*)(K + gb);
        float4 v4 = *(const float4*)(V + gb);
        sk[r * SB + c0 + 0] = f2tf(phi(k4.x));
        sk[r * SB + c0 + 1] = f2tf(phi(k4.y));
        sk[r * SB + c0 + 2] = f2tf(phi(k4.z));
        sk[r * SB + c0 + 3] = f2tf(phi(k4.w));
        sv[r * SB + c0 + 0] = f2tf(v4.x);
        sv[r * SB + c0 + 1] = f2tf(v4.y);
        sv[r * SB + c0 + 2] = f2tf(v4.z);
        sv[r * SB + c0 + 3] = f2tf(v4.w);
    }
    __syncthreads();

    {
        int d = tid & 63, part = tid >> 6;
        float s = 0.f;
        #pragma unroll 8
        for (int c = part * 32; c < part * 32 + 32; c++) s += sk[c * SB + d];
        sred[part * 64 + d] = s;
    }

    const int d0 = (wid >> 1) * 16, oc = (wid & 1) * 32;
    float cD[4][4];
    #pragma unroll
    for (int nj = 0; nj < 4; nj++)
        #pragma unroll
        for (int q = 0; q < 4; q++) cD[nj][q] = 0.f;

    #pragma unroll
    for (int kk = 0; kk < 16; kk++) {
        int kr = kk * 8 + tg;
        uint32_t a0 = __float_as_uint(sk[kr * SB + d0 + gid]);
        uint32_t a1 = __float_as_uint(sk[kr * SB + d0 + 8 + gid]);
        uint32_t a2 = __float_as_uint(sk[(kr + 4) * SB + d0 + gid]);
        uint32_t a3 = __float_as_uint(sk[(kr + 4) * SB + d0 + 8 + gid]);
        #pragma unroll
        for (int nj = 0; nj < 4; nj++) {
            uint32_t b0 = __float_as_uint(sv[kr * SB + oc + nj * 8 + gid]);
            uint32_t b1 = __float_as_uint(sv[(kr + 4) * SB + oc + nj * 8 + gid]);
            mma8(cD[nj], a0, a1, a2, a3, b0, b1);
        }
    }

    float* dst = g_kv + (size_t)b * (DD * MM);
    #pragma unroll
    for (int nj = 0; nj < 4; nj++) {
        int col = oc + nj * 8 + 2 * tg;
        *(float2*)(dst + (d0 + gid) * MM + col)     = make_float2(cD[nj][0], cD[nj][1]);
        *(float2*)(dst + (d0 + 8 + gid) * MM + col) = make_float2(cD[nj][2], cD[nj][3]);
    }

    __syncthreads();
    if (tid < 64)
        g_ks[(size_t)b * DD + tid] = sred[tid] + sred[64 + tid] + sred[128 + tid] + sred[192 + tid];
}

// ---------------------------------------------------------------------------
// k_scan: exact R5 version. grid (64,4)x256.
// ---------------------------------------------------------------------------
__global__ __launch_bounds__(256, 4)
void k_scan() {
    const int nh = blockIdx.x, n = nh >> 4, h = nh & 15;
    const int pos = blockIdx.y * 1024 + threadIdx.x * 4;
    float4 acc = make_float4(0.f, 0.f, 0.f, 0.f);
    size_t base0 = ((size_t)(n * GG * HH + h)) * (DD * MM) + pos;
    float4 nxt = *(const float4*)&g_kv[base0];
    for (int g = 0; g < GG; g++) {
        float4 cur = nxt;
        size_t base = ((size_t)((n * GG + g) * HH + h)) * (DD * MM) + pos;
        if (g + 1 < GG) {
            size_t basen = ((size_t)((n * GG + g + 1) * HH + h)) * (DD * MM) + pos;
            nxt = *(const float4*)&g_kv[basen];
        }
        *(float4*)&g_kvp[base] = acc;
        acc.x += cur.x; acc.y += cur.y; acc.z += cur.z; acc.w += cur.w;
    }
    if (blockIdx.y == 0 && threadIdx.x < DD) {
        float a = 0.f;
        for (int g = 0; g < GG; g++) {
            size_t off = (size_t)((n * GG + g) * HH + h) * DD + threadIdx.x;
            g_ksp[off] = a;
            a += g_ks[off];
        }
    }
}

// ---------------------------------------------------------------------------
// k_main: causal-trimmed fused attention. 512 threads:
//   phase 2: warps 0-3 diagonal 32x32 S blocks (mask+rowsum);
//            warps 4-7 three below-diagonal 16x32 S blocks each;
//            warps 8-15 O_inter (row-pair (gr,7-gr) x 32 cols)
//   phase 3: warps 8-15 O_intra with K trimmed to 2gr+2 steps per row group;
//            warps 0-3 z
// ---------------------------------------------------------------------------
#define OFF_SQ   0
#define OFF_SK   (CC*SA)
#define OFF_SV   (OFF_SK + CC*SA)
#define OFF_SS   (OFF_SV + CC*SB)
#define OFF_KVP  (OFF_SS + CC*SSW)
#define OFF_KSP  (OFF_KVP + DD*SB)
#define OFF_ZP   (OFF_KSP + DD)        // [4][CC]
#define OFF_Z    (OFF_ZP + 4*CC)
#define SM3_FLOATS (OFF_Z + CC)
#define SMEM3  (SM3_FLOATS * 4)

__global__ __launch_bounds__(512, 1)
void k_main(const float* __restrict__ Q, const float* __restrict__ K,
            const float* __restrict__ V, float* __restrict__ O) {
    extern __shared__ float sm[];
    float* sq   = sm + OFF_SQ;
    float* sk   = sm + OFF_SK;
    float* sv   = sm + OFF_SV;
    float* sS   = sm + OFF_SS;
    float* skvp = sm + OFF_KVP;
    float* sksp = sm + OFF_KSP;
    float* szp  = sm + OFF_ZP;
    float* sz   = sm + OFF_Z;

    const int tid = threadIdx.x, wid = tid >> 5, lane = tid & 31;
    const int gid = lane >> 2, tg = lane & 3;
    const int b = blockIdx.x, h = b & 15, g = (b >> 4) & 31, n = b >> 9;

    // ---- loads ----
    #pragma unroll
    for (int it = 0; it < 4; it++) {
        int idx = tid + it * 512;
        int r = idx >> 4, c0 = (idx & 15) * 4;
        int gb = ((n * LL + g * CC + r) * HH + h) * DD + c0;
        float4 q4 = *(const float4*)(Q + gb);
        float4 k4 = *(const float4*)(K + gb);
        float4 v4 = *(const float4*)(V + gb);
        sq[r * SA + c0 + 0] = f2tf(phi(q4.x));
        sq[r * SA + c0 + 1] = f2tf(phi(q4.y));
        sq[r * SA + c0 + 2] = f2tf(phi(q4.z));
        sq[r * SA + c0 + 3] = f2tf(phi(q4.w));
        sk[r * SA + c0 + 0] = f2tf(phi(k4.x));
        sk[r * SA + c0 + 1] = f2tf(phi(k4.y));
        sk[r * SA + c0 + 2] = f2tf(phi(k4.z));
        sk[r * SA + c0 + 3] = f2tf(phi(k4.w));
        sv[r * SB + c0 + 0] = f2tf(v4.x);
        sv[r * SB + c0 + 1] = f2tf(v4.y);
        sv[r * SB + c0 + 2] = f2tf(v4.z);
        sv[r * SB + c0 + 3] = f2tf(v4.w);
    }
    {
        const float* src = g_kvp + (size_t)b * (DD * MM);
        #pragma unroll
        for (int it = 0; it < 2; it++) {
            int idx = tid + it * 512;
            int d = idx >> 4, m0 = (idx & 15) * 4;
            float4 s4 = *(const float4*)(src + d * MM + m0);
            skvp[d * SB + m0 + 0] = f2tf(s4.x);
            skvp[d * SB + m0 + 1] = f2tf(s4.y);
            skvp[d * SB + m0 + 2] = f2tf(s4.z);
            skvp[d * SB + m0 + 3] = f2tf(s4.w);
        }
        if (tid < DD) sksp[tid] = g_ksp[(size_t)b * DD + tid];
    }
    __syncthreads();   // (A)

    // O-warp tile identities (row pair gr, 7-gr; one 32-col group)
    const int widq = wid - 8;
    const int gra = widq >> 1, grb = 7 - gra;
    const int ra = gra * 16, rb = grb * 16;
    const int oc = (widq & 1) * 32;
    float cA[4][4], cB[4][4];

    if (wid < 4) {
        // ---- diagonal 32x32 S block (rg = wid) ----
        const int r0 = wid * 32, c0g = wid * 32;
        float cS[2][4][4];
        #pragma unroll
        for (int mi = 0; mi < 2; mi++)
            #pragma unroll
            for (int nj = 0; nj < 4; nj++)
                #pragma unroll
                for (int q = 0; q < 4; q++) cS[mi][nj][q] = 0.f;

        #pragma unroll
        for (int kk = 0; kk < 8; kk++) {
            int kc = kk * 8 + tg;
            uint32_t a[2][4];
            #pragma unroll
            for (int mi = 0; mi < 2; mi++) {
                int ar = r0 + mi * 16;
                a[mi][0] = __float_as_uint(sq[(ar + gid) * SA + kc]);
                a[mi][1] = __float_as_uint(sq[(ar + 8 + gid) * SA + kc]);
                a[mi][2] = __float_as_uint(sq[(ar + gid) * SA + kc + 4]);
                a[mi][3] = __float_as_uint(sq[(ar + 8 + gid) * SA + kc + 4]);
            }
            #pragma unroll
            for (int nj = 0; nj < 4; nj++) {
                uint32_t b0 = __float_as_uint(sk[(c0g + nj * 8 + gid) * SA + kc]);
                uint32_t b1 = __float_as_uint(sk[(c0g + nj * 8 + gid) * SA + kc + 4]);
                mma8(cS[0][nj], a[0][0], a[0][1], a[0][2], a[0][3], b0, b1);
                mma8(cS[1][nj], a[1][0], a[1][1], a[1][2], a[1][3], b0, b1);
            }
        }
        #pragma unroll
        for (int mi = 0; mi < 2; mi++) {
            int rlo = r0 + mi * 16 + gid, rhi = rlo + 8;
            float zlo = 0.f, zhi = 0.f;
            #pragma unroll
            for (int nj = 0; nj < 4; nj++) {
                int c0 = c0g + nj * 8 + 2 * tg, c1 = c0 + 1;
                float s0 = (c0 <= rlo) ? cS[mi][nj][0] : 0.f;
                float s1 = (c1 <= rlo) ? cS[mi][nj][1] : 0.f;
                float s2 = (c0 <= rhi) ? cS[mi][nj][2] : 0.f;
                float s3 = (c1 <= rhi) ? cS[mi][nj][3] : 0.f;
                zlo += s0 + s1;
                zhi += s2 + s3;
                *(float2*)&sS[rlo * SSW + c0] = make_float2(f2tf(s0), f2tf(s1));
                *(float2*)&sS[rhi * SSW + c0] = make_float2(f2tf(s2), f2tf(s3));
            }
            zlo += __shfl_xor_sync(0xffffffffu, zlo, 1);
            zlo += __shfl_xor_sync(0xffffffffu, zlo, 2);
            zhi += __shfl_xor_sync(0xffffffffu, zhi, 1);
            zhi += __shfl_xor_sync(0xffffffffu, zhi, 2);
            if (tg == 0) {
                szp[wid * CC + rlo] = zlo;
                szp[wid * CC + rhi] = zhi;
            }
        }
    } else if (wid < 8) {
        // ---- three below-diagonal 16x32 S blocks (no masking) ----
        const int w = wid - 4;
        // subtile tables: 16-row group gr (rows gr*16..), 32-col group cg
        const int GRt[4][3] = {{2,4,6},{3,5,7},{4,5,6},{7,6,7}};
        const int CGt[4][3] = {{0,0,0},{0,0,0},{1,1,1},{1,2,2}};
        #pragma unroll
        for (int t = 0; t < 3; t++) {
            const int gr = GRt[w][t], cg = CGt[w][t];
            const int r0 = gr * 16, c0g = cg * 32;
            float cT[4][4];
            #pragma unroll
            for (int nj = 0; nj < 4; nj++)
                #pragma unroll
                for (int q = 0; q < 4; q++) cT[nj][q] = 0.f;

            #pragma unroll
            for (int kk = 0; kk < 8; kk++) {
                int kc = kk * 8 + tg;
                uint32_t a0 = __float_as_uint(sq[(r0 + gid) * SA + kc]);
                uint32_t a1 = __float_as_uint(sq[(r0 + 8 + gid) * SA + kc]);
                uint32_t a2 = __float_as_uint(sq[(r0 + gid) * SA + kc + 4]);
                uint32_t a3 = __float_as_uint(sq[(r0 + 8 + gid) * SA + kc + 4]);
                #pragma unroll
                for (int nj = 0; nj < 4; nj++) {
                    uint32_t b0 = __float_as_uint(sk[(c0g + nj * 8 + gid) * SA + kc]);
                    uint32_t b1 = __float_as_uint(sk[(c0g + nj * 8 + gid) * SA + kc + 4]);
                    mma8(cT[nj], a0, a1, a2, a3, b0, b1);
                }
            }
            int rlo = r0 + gid, rhi = rlo + 8;
            float zlo = 0.f, zhi = 0.f;
            #pragma unroll
            for (int nj = 0; nj < 4; nj++) {
                int c0 = c0g + nj * 8 + 2 * tg;
                zlo += cT[nj][0] + cT[nj][1];
                zhi += cT[nj][2] + cT[nj][3];
                *(float2*)&sS[rlo * SSW + c0] = make_float2(f2tf(cT[nj][0]), f2tf(cT[nj][1]));
                *(float2*)&sS[rhi * SSW + c0] = make_float2(f2tf(cT[nj][2]), f2tf(cT[nj][3]));
            }
            zlo += __shfl_xor_sync(0xffffffffu, zlo, 1);
            zlo += __shfl_xor_sync(0xffffffffu, zlo, 2);
            zhi += __shfl_xor_sync(0xffffffffu, zhi, 1);
            zhi += __shfl_xor_sync(0xffffffffu, zhi, 2);
            if (tg == 0) {
                szp[cg * CC + rlo] = zlo;
                szp[cg * CC + rhi] = zhi;
            }
        }
    } else {
        // ---- O_inter = phi(q) @ kvp : two 16x32 tiles (rows ra, rb), K=64 ----
        #pragma unroll
        for (int nj = 0; nj < 4; nj++)
            #pragma unroll
            for (int q = 0; q < 4; q++) { cA[nj][q] = 0.f; cB[nj][q] = 0.f; }

        #pragma unroll
        for (int kk = 0; kk < 8; kk++) {
            int kc = kk * 8 + tg;
            uint32_t aA0 = __float_as_uint(sq[(ra + gid) * SA + kc]);
            uint32_t aA1 = __float_as_uint(sq[(ra + 8 + gid) * SA + kc]);
            uint32_t aA2 = __float_as_uint(sq[(ra + gid) * SA + kc + 4]);
            uint32_t aA3 = __float_as_uint(sq[(ra + 8 + gid) * SA + kc + 4]);
            uint32_t aB0 = __float_as_uint(sq[(rb + gid) * SA + kc]);
            uint32_t aB1 = __float_as_uint(sq[(rb + 8 + gid) * SA + kc]);
            uint32_t aB2 = __float_as_uint(sq[(rb + gid) * SA + kc + 4]);
            uint32_t aB3 = __float_as_uint(sq[(rb + 8 + gid) * SA + kc + 4]);
            #pragma unroll
            for (int nj = 0; nj < 4; nj++) {
                uint32_t b0 = __float_as_uint(skvp[kc * SB + oc + nj * 8 + gid]);
                uint32_t b1 = __float_as_uint(skvp[(kc + 4) * SB + oc + nj * 8 + gid]);
                mma8(cA[nj], aA0, aA1, aA2, aA3, b0, b1);
                mma8(cB[nj], aB0, aB1, aB2, aB3, b0, b1);
            }
        }
    }
    __syncthreads();   // (B)

    if (wid < 8) {
        // ---- z (warps 0-3): z[r] = EPS + q.ksum_prev + sum_{cg<=rg} szp[cg][r] ----
        if (tid < CC) {
            int r = tid, rg = r >> 5;
            float qd = EPS;
            #pragma unroll 8
            for (int d = 0; d < DD; d++) qd += sq[r * SA + d] * sksp[d];
            float s = szp[r];                       // cg=0 always present
            if (rg >= 1) s += szp[CC + r];
            if (rg >= 2) s += szp[2 * CC + r];
            if (rg >= 3) s += szp[3 * CC + r];
            sz[r] = qd + s;
        }
    } else {
        // ---- O_intra: K trimmed to 2gr+2 steps per row tile ----
        const int nka = 2 * gra + 2, nkb = 2 * grb + 2;
        for (int kk = 0; kk < nka; kk++) {
            int kc = kk * 8 + tg;
            uint32_t a0 = __float_as_uint(sS[(ra + gid) * SSW + kc]);
            uint32_t a1 = __float_as_uint(sS[(ra + 8 + gid) * SSW + kc]);
            uint32_t a2 = __float_as_uint(sS[(ra + gid) * SSW + kc + 4]);
            uint32_t a3 = __float_as_uint(sS[(ra + 8 + gid) * SSW + kc + 4]);
            #pragma unroll
            for (int nj = 0; nj < 4; nj++) {
                uint32_t b0 = __float_as_uint(sv[kc * SB + oc + nj * 8 + gid]);
                uint32_t b1 = __float_as_uint(sv[(kc + 4) * SB + oc + nj * 8 + gid]);
                mma8(cA[nj], a0, a1, a2, a3, b0, b1);
            }
        }
        for (int kk = 0; kk < nkb; kk++) {
            int kc = kk * 8 + tg;
            uint32_t a0 = __float_as_uint(sS[(rb + gid) * SSW + kc]);
            uint32_t a1 = __float_as_uint(sS[(rb + 8 + gid) * SSW + kc]);
            uint32_t a2 = __float_as_uint(sS[(rb + gid) * SSW + kc + 4]);
            uint32_t a3 = __float_as_uint(sS[(rb + 8 + gid) * SSW + kc + 4]);
            #pragma unroll
            for (int nj = 0; nj < 4; nj++) {
                uint32_t b0 = __float_as_uint(sv[kc * SB + oc + nj * 8 + gid]);
                uint32_t b1 = __float_as_uint(sv[(kc + 4) * SB + oc + nj * 8 + gid]);
                mma8(cB[nj], a0, a1, a2, a3, b0, b1);
            }
        }
    }
    __syncthreads();   // (C)

    if (wid >= 8) {
        // ---- epilogue: both tiles ----
        int rlo = ra + gid, rhi = rlo + 8;
        float izlo = 1.f / sz[rlo], izhi = 1.f / sz[rhi];
        float* oblo = O + ((size_t)((n * LL + g * CC + rlo) * HH + h)) * MM;
        float* obhi = O + ((size_t)((n * LL + g * CC + rhi) * HH + h)) * MM;
        #pragma unroll
        for (int nj = 0; nj < 4; nj++) {
            int c0 = oc + nj * 8 + 2 * tg;
            *(float2*)(oblo + c0) = make_float2(cA[nj][0] * izlo, cA[nj][1] * izlo);
            *(float2*)(obhi + c0) = make_float2(cA[nj][2] * izhi, cA[nj][3] * izhi);
        }
        rlo = rb + gid; rhi = rlo + 8;
        izlo = 1.f / sz[rlo]; izhi = 1.f / sz[rhi];
        oblo = O + ((size_t)((n * LL + g * CC + rlo) * HH + h)) * MM;
        obhi = O + ((size_t)((n * LL + g * CC + rhi) * HH + h)) * MM;
        #pragma unroll
        for (int nj = 0; nj < 4; nj++) {
            int c0 = oc + nj * 8 + 2 * tg;
            *(float2*)(oblo + c0) = make_float2(cB[nj][0] * izlo, cB[nj][1] * izlo);
            *(float2*)(obhi + c0) = make_float2(cB[nj][2] * izhi, cB[nj][3] * izhi);
        }
    }
}

// ---------------------------------------------------------------------------
extern "C" void kernel_launch(void* const* d_in, const int* in_sizes, int n_in,
                              void* d_out, int out_size) {
    const float* Q = (const float*)d_in[0];
    const float* K = (const float*)d_in[1];
    const float* V = (const float*)d_in[2];
    float* O = (float*)d_out;

    cudaFuncSetAttribute(k_state, cudaFuncAttributeMaxDynamicSharedMemorySize, SMEM1);
    cudaFuncSetAttribute(k_main,  cudaFuncAttributeMaxDynamicSharedMemorySize, SMEM3);

    k_state<<<NTILE, 256, SMEM1>>>(K, V);
    k_scan<<<dim3(NB * HH, 4), 256>>>();
    k_main<<<NTILE, 512, SMEM3>>>(Q, K, V, O);
}